// round 5
// baseline (speedup 1.0000x reference)
#include <cuda_runtime.h>

// Problem geometry is fixed by the dataset.
#define HH  64
#define WWI 64
#define HWN 4096
#define BBN 4

constexpr int BM = 128;   // out-channel tile
constexpr int BN = 128;   // pixel tile (2 rows of 64)
constexpr int BK = 8;     // input-channel chunk

// ---------------- packed fp32x2 helpers (sm_103a FFMA2 path) ---------------
#define FMA2(acc, a, b) \
    asm("fma.rn.f32x2 %0, %1, %2, %0;" : "+l"(acc) : "l"(a), "l"(b))
#define PACK2(d, lo, hi) \
    asm("mov.b64 %0, {%1, %2};" : "=l"(d) : "f"(lo), "f"(hi))
#define UNPACK2(lo, hi, v) \
    asm("mov.b64 {%0, %1}, %2;" : "=f"(lo), "=f"(hi) : "l"(v))

// ---------------- scratch (static device memory; no allocation) -------------
__device__ float g_h1[(size_t)BBN * 1024 * HWN];  // deform1 output  (67 MB)
__device__ float g_h2[(size_t)BBN * 256  * HWN];  // conv1+bn
__device__ float g_h3[(size_t)BBN * 256  * HWN];  // deform2
__device__ float g_h4[(size_t)BBN * 256  * HWN];  // conv2+bn
__device__ float g_h5[(size_t)BBN * 256  * HWN];  // deform3
__device__ float g_sc1[256],  g_bi1[256];
__device__ float g_sc2[256],  g_bi2[256];
__device__ float g_sc3[1024], g_bi3[1024];

// ---------------- BN fold: scale = g*rsqrt(v+eps), bias = b - m*scale -------
__global__ void bnprep_kernel(const float* __restrict__ g, const float* __restrict__ b,
                              const float* __restrict__ m, const float* __restrict__ v,
                              float* __restrict__ sc, float* __restrict__ bi, int C) {
    int i = blockIdx.x * blockDim.x + threadIdx.x;
    if (i < C) {
        float inv = g[i] * rsqrtf(v[i] + 1e-5f);
        sc[i] = inv;
        bi[i] = b[i] - m[i] * inv;
    }
}

// ---------------- fused implicit-GEMM conv ---------------------------------
// KS      : 1 or 3 (pad = KS/2), weights [Cout, Cin, KS*KS] (OIHW)
// DEFORM  : conv predicts (dy,dx) pairs (Cout = 2*Cin); epilogue bilinearly
//           resamples `in` at grid+offset and writes [B, Cin, H, W]
// AFFINE  : per-channel scale/bias (folded BN)
// RELU    : final relu
// Thread tile: 8 oc x 8 px, with pixels handled as 4 f32x2 pairs.
// Pixel of (jp, c):  p = 2*tx + 32*jp + c   (tx 0..15, jp 0..3, c 0..1)
// grid: x = B * (HW / BN) = 128 pixel tiles, y = Cout / BM
template<int KS, bool DEFORM, bool AFFINE, bool RELU>
__global__ __launch_bounds__(256)
void conv_kernel(const float* __restrict__ in, const float* __restrict__ wgt,
                 const float* __restrict__ cbias,
                 const float* __restrict__ scale, const float* __restrict__ bias,
                 float* __restrict__ out, int Cin, int Cout)
{
    constexpr int TAPS  = KS * KS;
    constexpr int XROWS = (KS == 3) ? 4 : 2;
    constexpr int XCOLS = (KS == 3) ? 66 : 64;

    __shared__ float sW[BK * TAPS][BM + 1];     // +1: odd stride -> conflict-free STS
    __shared__ float sX[BK][XROWS][XCOLS];

    const int tid = threadIdx.x;
    const int tx  = tid & 15;     // pixel group
    const int ty  = tid >> 4;     // oc group
    const int pt  = blockIdx.x;
    const int b   = pt >> 5;              // 32 pixel tiles per image
    const int y0  = (pt & 31) << 1;       // first of 2 rows
    const int oc0 = blockIdx.y * BM;

    unsigned long long acc2[8][4];
#pragma unroll
    for (int i = 0; i < 8; i++)
#pragma unroll
        for (int jp = 0; jp < 4; jp++) acc2[i][jp] = 0ULL;

    const int nChunks = Cin / BK;
    for (int kc = 0; kc < nChunks; kc++) {
        const int ic0 = kc * BK;

        // ---- weights: global [oc][ic*TAPS..] contiguous per oc -> coalesced
        const float* wbase = wgt + (size_t)oc0 * Cin * TAPS + (size_t)ic0 * TAPS;
#pragma unroll 4
        for (int i = tid; i < BK * TAPS * BM; i += 256) {
            int m = i / (BK * TAPS);
            int j = i - m * (BK * TAPS);           // j = kk*TAPS + t
            sW[j][m] = wbase[(size_t)m * (Cin * TAPS) + j];
        }

        // ---- input tile (+halo for KS==3)
        const float* ibase = in + (size_t)(b * Cin + ic0) * HWN;
        if (KS == 3) {
#pragma unroll 2
            for (int i = tid; i < BK * 4 * 66; i += 256) {
                int kk = i / 264;
                int r2 = i - kk * 264;
                int r  = r2 / 66;
                int c  = r2 - r * 66;
                int gy = y0 - 1 + r;
                int gx = c - 1;
                float v = 0.f;
                if ((unsigned)gy < 64u && (unsigned)gx < 64u)
                    v = ibase[(size_t)kk * HWN + gy * 64 + gx];
                sX[kk][r][c] = v;
            }
        } else {
#pragma unroll 2
            for (int i = tid; i < BK * 128; i += 256) {
                int kk = i >> 7;
                int p  = i & 127;
                sX[kk][p >> 6][p & 63] =
                    ibase[(size_t)kk * HWN + (y0 + (p >> 6)) * 64 + (p & 63)];
            }
        }
        __syncthreads();

        // ---- 128x128x(BK*TAPS) register-tiled MACs via FFMA2 (f32x2)
#pragma unroll 2
        for (int kk = 0; kk < BK; kk++) {
#pragma unroll
            for (int t = 0; t < TAPS; t++) {
                unsigned long long a2[8], b2[4];
#pragma unroll
                for (int i = 0; i < 8; i++) {
                    float a = sW[kk * TAPS + t][ty * 8 + i];
                    PACK2(a2[i], a, a);
                }
#pragma unroll
                for (int jp = 0; jp < 4; jp++) {
                    int p  = 2 * tx + 32 * jp;
                    int row, col;
                    if (KS == 3) { row = (p >> 6) + t / KS; col = (p & 63) + t % KS; }
                    else         { row = (p >> 6);          col = (p & 63); }
                    float blo = sX[kk][row][col];
                    float bhi = sX[kk][row][col + 1];
                    PACK2(b2[jp], blo, bhi);
                }
#pragma unroll
                for (int i = 0; i < 8; i++)
#pragma unroll
                    for (int jp = 0; jp < 4; jp++)
                        FMA2(acc2[i][jp], a2[i], b2[jp]);
            }
        }
        __syncthreads();
    }

    // ---- unpack accumulators: acc[i][j], pixel p(j) = 2*tx + 32*(j>>1) + (j&1)
    float acc[8][8];
#pragma unroll
    for (int i = 0; i < 8; i++)
#pragma unroll
        for (int jp = 0; jp < 4; jp++)
            UNPACK2(acc[i][2 * jp], acc[i][2 * jp + 1], acc2[i][jp]);

    // -------------------------- epilogue ------------------------------------
    if (DEFORM) {
        // acc rows hold interleaved (dy,dx) channels; 4 complete pairs/thread.
        const int C   = Cout >> 1;          // == Cin
        const int ocb = oc0 + ty * 8;       // even
        float cb[8];
#pragma unroll
        for (int i = 0; i < 8; i++) cb[i] = cbias[ocb + i];

#pragma unroll
        for (int t2 = 0; t2 < 4; t2++) {
            const int c = (ocb >> 1) + t2;
            const float* src = in  + (size_t)(b * Cin + c) * HWN;
            float*       dst = out + (size_t)(b * C   + c) * HWN;
#pragma unroll
            for (int j = 0; j < 8; j++) {
                int   p  = 2 * tx + 32 * (j >> 1) + (j & 1);
                int   gy = y0 + (p >> 6);
                int   gx = p & 63;
                float dy = acc[2 * t2][j]     + cb[2 * t2];
                float dx = acc[2 * t2 + 1][j] + cb[2 * t2 + 1];
                float py = fminf(fmaxf((float)gy + dy, 0.f), 63.f);
                float px = fminf(fmaxf((float)gx + dx, 0.f), 63.f);
                float fy = floorf(py), fx = floorf(px);
                int  iy0 = (int)fy,  ix0 = (int)fx;
                int  iy1 = min(iy0 + 1, 63), ix1 = min(ix0 + 1, 63);
                float wy = py - fy, wx = px - fx;
                const float* r0 = src + iy0 * 64;
                const float* r1 = src + iy1 * 64;
                float v00 = r0[ix0], v01 = r0[ix1];
                float v10 = r1[ix0], v11 = r1[ix1];
                float vt = v00 + (v01 - v00) * wx;
                float vb = v10 + (v11 - v10) * wx;
                dst[gy * 64 + gx] = vt + (vb - vt) * wy;
            }
        }
    } else {
#pragma unroll
        for (int i = 0; i < 8; i++) {
            int oc = oc0 + ty * 8 + i;
            float s  = AFFINE ? scale[oc] : 1.f;
            float bo = AFFINE ? bias[oc]  : 0.f;
            float* dst = out + (size_t)(b * Cout + oc) * HWN;
#pragma unroll
            for (int j = 0; j < 8; j++) {
                int p = 2 * tx + 32 * (j >> 1) + (j & 1);
                float v = acc[i][j] * s + bo;
                if (RELU) v = fmaxf(v, 0.f);
                dst[(y0 + (p >> 6)) * 64 + (p & 63)] = v;
            }
        }
    }
}

// ---------------------------------------------------------------------------
extern "C" void kernel_launch(void* const* d_in, const int* in_sizes, int n_in,
                              void* d_out, int out_size)
{
    (void)n_in; (void)out_size;

    // Resolve input ordering from in_sizes (see R1 notes).
    //  A (reference signature): x, ow1, ob1, w1, g1,b1,m1,v1, ow2, ob2, w2, ...
    //  B (setup_inputs dict):   x, ow1, ob1, ow2, ob2, ow3, ob3, w1, w2, w3, g1,...
    // Discriminator: in_sizes[3] is 262144 (w1) in order A, 1179648 (ow2) in B.
    const float *x, *ow1, *ob1, *ow2, *ob2, *ow3, *ob3, *w1, *w2, *w3;
    const float *g1, *b1, *m1, *v1, *g2, *b2, *m2, *v2, *g3, *b3, *m3, *v3;

    x   = (const float*)d_in[0];
    ow1 = (const float*)d_in[1];
    ob1 = (const float*)d_in[2];
    if (in_sizes[3] == 262144) {
        w1  = (const float*)d_in[3];
        g1  = (const float*)d_in[4];  b1 = (const float*)d_in[5];
        m1  = (const float*)d_in[6];  v1 = (const float*)d_in[7];
        ow2 = (const float*)d_in[8];  ob2 = (const float*)d_in[9];
        w2  = (const float*)d_in[10];
        g2  = (const float*)d_in[11]; b2 = (const float*)d_in[12];
        m2  = (const float*)d_in[13]; v2 = (const float*)d_in[14];
        ow3 = (const float*)d_in[15]; ob3 = (const float*)d_in[16];
        w3  = (const float*)d_in[17];
        g3  = (const float*)d_in[18]; b3 = (const float*)d_in[19];
        m3  = (const float*)d_in[20]; v3 = (const float*)d_in[21];
    } else {
        ow2 = (const float*)d_in[3];  ob2 = (const float*)d_in[4];
        ow3 = (const float*)d_in[5];  ob3 = (const float*)d_in[6];
        w1  = (const float*)d_in[7];
        w2  = (const float*)d_in[8];
        w3  = (const float*)d_in[9];
        g1  = (const float*)d_in[10]; b1 = (const float*)d_in[11];
        m1  = (const float*)d_in[12]; v1 = (const float*)d_in[13];
        g2  = (const float*)d_in[14]; b2 = (const float*)d_in[15];
        m2  = (const float*)d_in[16]; v2 = (const float*)d_in[17];
        g3  = (const float*)d_in[18]; b3 = (const float*)d_in[19];
        m3  = (const float*)d_in[20]; v3 = (const float*)d_in[21];
    }
    float* out = (float*)d_out;

    float *h1, *h2, *h3, *h4, *h5;
    float *sc1, *bi1, *sc2, *bi2, *sc3, *bi3;
    cudaGetSymbolAddress((void**)&h1,  g_h1);
    cudaGetSymbolAddress((void**)&h2,  g_h2);
    cudaGetSymbolAddress((void**)&h3,  g_h3);
    cudaGetSymbolAddress((void**)&h4,  g_h4);
    cudaGetSymbolAddress((void**)&h5,  g_h5);
    cudaGetSymbolAddress((void**)&sc1, g_sc1);
    cudaGetSymbolAddress((void**)&bi1, g_bi1);
    cudaGetSymbolAddress((void**)&sc2, g_sc2);
    cudaGetSymbolAddress((void**)&bi2, g_bi2);
    cudaGetSymbolAddress((void**)&sc3, g_sc3);
    cudaGetSymbolAddress((void**)&bi3, g_bi3);

    // Fold BN params.
    bnprep_kernel<<<1, 256>>>(g1, b1, m1, v1, sc1, bi1, 256);
    bnprep_kernel<<<1, 256>>>(g2, b2, m2, v2, sc2, bi2, 256);
    bnprep_kernel<<<4, 256>>>(g3, b3, m3, v3, sc3, bi3, 1024);

    const dim3 blk(256);

    // stage 1: offset conv (1024 -> 2048) fused with bilinear deform of x -> h1
    conv_kernel<3, true,  false, false><<<dim3(128, 16), blk>>>(x,  ow1, ob1, nullptr, nullptr, h1, 1024, 2048);
    // conv1 1x1 + BN: 1024 -> 256
    conv_kernel<1, false, true,  false><<<dim3(128, 2),  blk>>>(h1, w1, nullptr, sc1, bi1, h2, 1024, 256);
    // stage 2: offset conv (256 -> 512) fused deform of h2 -> h3
    conv_kernel<3, true,  false, false><<<dim3(128, 4),  blk>>>(h2, ow2, ob2, nullptr, nullptr, h3, 256, 512);
    // conv2 3x3 + BN: 256 -> 256
    conv_kernel<3, false, true,  false><<<dim3(128, 2),  blk>>>(h3, w2, nullptr, sc2, bi2, h4, 256, 256);
    // stage 3: offset conv (256 -> 512) fused deform of h4 -> h5
    conv_kernel<3, true,  false, false><<<dim3(128, 4),  blk>>>(h4, ow3, ob3, nullptr, nullptr, h5, 256, 512);
    // conv3 1x1 + BN + ReLU: 256 -> 1024 -> out
    conv_kernel<1, false, true,  true ><<<dim3(128, 8),  blk>>>(h5, w3, nullptr, sc3, bi3, out, 256, 1024);
}

// round 12
// speedup vs baseline: 2.4735x; 2.4735x over previous
#include <cuda_runtime.h>
#include <cuda_bf16.h>
#include <cstdint>

#define HWN 4096
#define BBN 4

// ---------------- static scratch (packed {bf16hi,bf16lo} u32) ---------------
__device__ uint32_t g_xp [(size_t)BBN * 1024 * HWN];
__device__ uint32_t g_h1 [(size_t)BBN * 1024 * HWN];
__device__ uint32_t g_h2 [(size_t)BBN * 256  * HWN];
__device__ uint32_t g_h3 [(size_t)BBN * 256  * HWN];
__device__ uint32_t g_h4 [(size_t)BBN * 256  * HWN];
__device__ uint32_t g_h5 [(size_t)BBN * 256  * HWN];
__device__ uint32_t g_wo1[(size_t)2048 * 9 * 1024];
__device__ uint32_t g_w1 [(size_t)256  * 1024];
__device__ uint32_t g_wo2[(size_t)512  * 9 * 256];
__device__ uint32_t g_w2 [(size_t)256  * 9 * 256];
__device__ uint32_t g_wo3[(size_t)512  * 9 * 256];
__device__ uint32_t g_w3 [(size_t)1024 * 256];
__device__ float g_sc1[256],  g_bi1[256];
__device__ float g_sc2[256],  g_bi2[256];
__device__ float g_sc3[1024], g_bi3[1024];

// ---------------- helpers ----------------------------------------------------
__device__ __forceinline__ uint32_t packbf(float x) {
    __nv_bfloat16 h = __float2bfloat16(x);
    float hf = __bfloat162float(h);
    __nv_bfloat16 l = __float2bfloat16(x - hf);
    return ((uint32_t)__bfloat16_as_ushort(h) << 16) | (uint32_t)__bfloat16_as_ushort(l);
}
__device__ __forceinline__ float unpackbf(uint32_t p) {
    return __uint_as_float(p & 0xffff0000u) + __uint_as_float(p << 16);
}
__device__ __forceinline__ uint32_t prmt(uint32_t a, uint32_t b, uint32_t s) {
    uint32_t r; asm("prmt.b32 %0, %1, %2, %3;" : "=r"(r) : "r"(a), "r"(b), "r"(s)); return r;
}

// m16n8k16 bf16 MMA, f32 accumulate (sm_80+ PTX: compiles in BOTH the sm_103a
// and portable compute_103 passes).
#define MMA_BF16(c, a, b) \
    asm volatile("mma.sync.aligned.m16n8k16.row.col.f32.bf16.bf16.f32 " \
        "{%0,%1,%2,%3}, {%4,%5,%6,%7}, {%8,%9}, {%0,%1,%2,%3};" \
        : "+f"((c)[0]), "+f"((c)[1]), "+f"((c)[2]), "+f"((c)[3]) \
        : "r"((a)[0]), "r"((a)[1]), "r"((a)[2]), "r"((a)[3]), \
          "r"((b)[0]), "r"((b)[1]))

// ---------------- prep kernels ----------------------------------------------
__global__ void bnprep_kernel(const float* __restrict__ g, const float* __restrict__ b,
                              const float* __restrict__ m, const float* __restrict__ v,
                              float* __restrict__ sc, float* __restrict__ bi, int C) {
    int i = blockIdx.x * blockDim.x + threadIdx.x;
    if (i < C) {
        float inv = g[i] * rsqrtf(v[i] + 1e-5f);
        sc[i] = inv;
        bi[i] = b[i] - m[i] * inv;
    }
}
__global__ void xprep_kernel(const float* __restrict__ x, uint32_t* __restrict__ xp, int n) {
    int i = blockIdx.x * blockDim.x + threadIdx.x;
    if (i < n) xp[i] = packbf(x[i]);
}
__global__ void wprep_kernel(const float* __restrict__ w, uint32_t* __restrict__ wp,
                             int Cin, int TAPS, int n) {
    int i = blockIdx.x * blockDim.x + threadIdx.x;
    if (i < n) {
        int ct = Cin * TAPS;
        int oc = i / ct;
        int r  = i - oc * ct;
        int ic = r / TAPS;
        int t  = r - ic * TAPS;
        wp[((size_t)oc * TAPS + t) * Cin + ic] = packbf(w[i]);
    }
}

// ---------------- fused conv via mma.sync -----------------------------------
// Tile: M=128 oc x N=128 px (2 image rows), K-chunk 64 input channels.
// 8 warps: warp w -> (mw = w&3) M-quadrant (32 oc), (nw = w>>2) N-half (64 px).
// Markidis bf16 split: acc += Ahi*Bhi + Ahi*Blo + Alo*Bhi  (error ~1.5e-5).
// EPI: 0 deform(pack out), 1 affine(pack), 2 affine+relu(f32 out).
static constexpr int DSMEM = 73728;

template<int TAPS, int EPI>
__global__ __launch_bounds__(256)
void mmaconv(const uint32_t* __restrict__ inp, const uint32_t* __restrict__ wp,
             const float* __restrict__ cbias,
             const float* __restrict__ sc, const float* __restrict__ bi,
             uint32_t* __restrict__ outp, float* __restrict__ outf,
             int Cin, int Cout)
{
    extern __shared__ uint32_t sm[];
    uint32_t* Ahi = sm;
    uint32_t* Alo = sm + 4608;
    uint32_t* Bhi = sm + 9216;
    uint32_t* Blo = sm + 13824;

    const int tid  = threadIdx.x;
    const int w    = tid >> 5, lane = tid & 31;
    const int mw   = w & 3, nw = w >> 2;
    const int bimg = blockIdx.x >> 5;
    const int y0   = (blockIdx.x & 31) << 1;
    const int oc0  = blockIdx.y << 7;

    float acc[2][8][4];
#pragma unroll
    for (int a = 0; a < 2; ++a)
#pragma unroll
        for (int b = 0; b < 8; ++b)
#pragma unroll
            for (int c = 0; c < 4; ++c) acc[a][b][c] = 0.f;

    const int n_chunks = TAPS * (Cin >> 6);
    for (int ch = 0; ch < n_chunks; ++ch) {
        const int tap = (TAPS == 9) ? (ch % 9) : 0;
        const int ic0 = ((TAPS == 9) ? (ch / 9) : ch) << 6;
        // BUGFIX (R10): for TAPS==1 the single tap is centered -> no shift.
        // (tap/3-1 gave -1,-1 for tap==0, silently shifting every 1x1 conv.)
        const int dyt = (TAPS == 9) ? (tap / 3 - 1) : 0;
        const int dxt = (TAPS == 9) ? (tap % 3 - 1) : 0;

        {   // stage A (weights): warp w -> oc rows w*16..+15, lane -> k-pair
            const uint32_t* wrow = wp + ((size_t)(oc0 + (w << 4)) * TAPS + tap) * Cin
                                      + ic0 + (lane << 1);
            const size_t rstride = (size_t)TAPS * Cin;
#pragma unroll 4
            for (int r = 0; r < 16; ++r) {
                uint2 p = *reinterpret_cast<const uint2*>(wrow + (size_t)r * rstride);
                int row = (w << 4) + r;
                Ahi[row * 36 + lane] = prmt(p.x, p.y, 0x7632u);
                Alo[row * 36 + lane] = prmt(p.x, p.y, 0x5410u);
            }
        }
        {   // stage B (pixels): B[n=px][k=ic], coalesced along px
            const uint32_t* ibase = inp + (size_t)bimg * Cin * HWN;
#pragma unroll
            for (int nb = 0; nb < 2; ++nb) {
                const int n  = (w << 4) + (nb << 3) + (lane & 7);
                const int gy = y0 + (n >> 6) + dyt;
                const int gx = (n & 63) + dxt;
                const bool ok = (TAPS == 1) ||
                                (((unsigned)gy < 64u) && ((unsigned)gx < 64u));
                const int gyc = ok ? gy : 0, gxc = ok ? gx : 0;
                const uint32_t* col = ibase + (size_t)(ic0 + ((lane >> 3) << 1)) * HWN
                                            + gyc * 64 + gxc;
#pragma unroll 4
                for (int m = 0; m < 8; ++m) {
                    const uint32_t* q = col + (size_t)(m << 3) * HWN;
                    uint32_t p0 = ok ? q[0]   : 0u;
                    uint32_t p1 = ok ? q[HWN] : 0u;
                    int pair = (lane >> 3) + (m << 2);
                    Bhi[n * 36 + pair] = prmt(p0, p1, 0x7632u);
                    Blo[n * 36 + pair] = prmt(p0, p1, 0x5410u);
                }
            }
        }
        __syncthreads();

#pragma unroll
        for (int ks = 0; ks < 4; ++ks) {
            uint32_t bh[8][2], bl[8][2];
#pragma unroll
            for (int nf = 0; nf < 8; ++nf) {
                int base = (nw * 64 + nf * 8 + (lane >> 2)) * 36 + ks * 8 + (lane & 3);
                bh[nf][0] = Bhi[base];     bh[nf][1] = Bhi[base + 4];
                bl[nf][0] = Blo[base];     bl[nf][1] = Blo[base + 4];
            }
            uint32_t ah[2][4], al[2][4];
#pragma unroll
            for (int mf = 0; mf < 2; ++mf) {
                int base = (mw * 32 + mf * 16 + (lane >> 2)) * 36 + ks * 8 + (lane & 3);
                ah[mf][0] = Ahi[base];       ah[mf][1] = Ahi[base + 288];   // row+8
                ah[mf][2] = Ahi[base + 4];   ah[mf][3] = Ahi[base + 292];
                al[mf][0] = Alo[base];       al[mf][1] = Alo[base + 288];
                al[mf][2] = Alo[base + 4];   al[mf][3] = Alo[base + 292];
            }
#pragma unroll
            for (int mf = 0; mf < 2; ++mf)
#pragma unroll
                for (int nf = 0; nf < 8; ++nf) {
                    MMA_BF16(acc[mf][nf], ah[mf], bh[nf]);
                    MMA_BF16(acc[mf][nf], ah[mf], bl[nf]);
                    MMA_BF16(acc[mf][nf], al[mf], bh[nf]);
                }
        }
        __syncthreads();
    }

    // ---- stage D fragments to SMEM so the epilogue gets a clean (oc,px) view
    float* Ds = (float*)sm;     // [128][130] f32, 66.5KB <= 73.7KB
#pragma unroll
    for (int mf = 0; mf < 2; ++mf)
#pragma unroll
        for (int nf = 0; nf < 8; ++nf) {
            int row = mw * 32 + mf * 16 + (lane >> 2);
            int col = nw * 64 + nf * 8 + 2 * (lane & 3);
            Ds[row * 130 + col]           = acc[mf][nf][0];
            Ds[row * 130 + col + 1]       = acc[mf][nf][1];
            Ds[(row + 8) * 130 + col]     = acc[mf][nf][2];
            Ds[(row + 8) * 130 + col + 1] = acc[mf][nf][3];
        }
    __syncthreads();

    const int tx = tid & 15, ty = tid >> 4;
    float a8[8][8];
#pragma unroll
    for (int i = 0; i < 8; ++i)
#pragma unroll
        for (int j = 0; j < 8; ++j)
            a8[i][j] = Ds[(ty * 8 + i) * 130 + tx * 8 + j];

    if (EPI == 0) {
        // deform epilogue: rows alternate (dy,dx); thread owns 4 pairs x 8 px
        const int Cc  = Cout >> 1;
        const int ocb = oc0 + ty * 8;
#pragma unroll
        for (int t2 = 0; t2 < 4; t2++) {
            const int c = (ocb >> 1) + t2;
            const uint32_t* src = inp + (size_t)(bimg * Cin + c) * HWN;
            uint32_t* dst = outp + (size_t)(bimg * Cc + c) * HWN;
            float cby = cbias[ocb + 2 * t2], cbx = cbias[ocb + 2 * t2 + 1];
#pragma unroll
            for (int j = 0; j < 8; j++) {
                int p = tx * 8 + j, gy = y0 + (p >> 6), gx = p & 63;
                float dy = a8[2 * t2][j] + cby;
                float dx = a8[2 * t2 + 1][j] + cbx;
                float py = fminf(fmaxf((float)gy + dy, 0.f), 63.f);
                float px = fminf(fmaxf((float)gx + dx, 0.f), 63.f);
                float fy = floorf(py), fx = floorf(px);
                int iy0 = (int)fy, ix0 = (int)fx;
                int iy1 = min(iy0 + 1, 63), ix1 = min(ix0 + 1, 63);
                float wy = py - fy, wx = px - fx;
                float v00 = unpackbf(src[iy0 * 64 + ix0]), v01 = unpackbf(src[iy0 * 64 + ix1]);
                float v10 = unpackbf(src[iy1 * 64 + ix0]), v11 = unpackbf(src[iy1 * 64 + ix1]);
                float vt = v00 + (v01 - v00) * wx;
                float vb = v10 + (v11 - v10) * wx;
                dst[gy * 64 + gx] = packbf(vt + (vb - vt) * wy);
            }
        }
    } else {
#pragma unroll
        for (int i = 0; i < 8; i++) {
            int oc = oc0 + ty * 8 + i;
            float s = sc[oc], bo = bi[oc];
#pragma unroll
            for (int j = 0; j < 8; j++) {
                int p = tx * 8 + j, gy = y0 + (p >> 6), gx = p & 63;
                float v = a8[i][j] * s + bo;
                size_t o = (size_t)(bimg * Cout + oc) * HWN + gy * 64 + gx;
                if (EPI == 1) outp[o] = packbf(v);
                else          outf[o] = fmaxf(v, 0.f);
            }
        }
    }
}

// ---------------------------------------------------------------------------
extern "C" void kernel_launch(void* const* d_in, const int* in_sizes, int n_in,
                              void* d_out, int out_size)
{
    (void)n_in; (void)out_size;
    const float *x, *ow1, *ob1, *ow2, *ob2, *ow3, *ob3, *w1, *w2, *w3;
    const float *g1, *b1, *m1, *v1, *g2, *b2, *m2, *v2, *g3, *b3, *m3, *v3;
    x   = (const float*)d_in[0];
    ow1 = (const float*)d_in[1];
    ob1 = (const float*)d_in[2];
    if (in_sizes[3] == 262144) {   // signature order
        w1  = (const float*)d_in[3];
        g1  = (const float*)d_in[4];  b1 = (const float*)d_in[5];
        m1  = (const float*)d_in[6];  v1 = (const float*)d_in[7];
        ow2 = (const float*)d_in[8];  ob2 = (const float*)d_in[9];
        w2  = (const float*)d_in[10];
        g2  = (const float*)d_in[11]; b2 = (const float*)d_in[12];
        m2  = (const float*)d_in[13]; v2 = (const float*)d_in[14];
        ow3 = (const float*)d_in[15]; ob3 = (const float*)d_in[16];
        w3  = (const float*)d_in[17];
        g3  = (const float*)d_in[18]; b3 = (const float*)d_in[19];
        m3  = (const float*)d_in[20]; v3 = (const float*)d_in[21];
    } else {                        // setup_inputs dict order
        ow2 = (const float*)d_in[3];  ob2 = (const float*)d_in[4];
        ow3 = (const float*)d_in[5];  ob3 = (const float*)d_in[6];
        w1  = (const float*)d_in[7];
        w2  = (const float*)d_in[8];
        w3  = (const float*)d_in[9];
        g1  = (const float*)d_in[10]; b1 = (const float*)d_in[11];
        m1  = (const float*)d_in[12]; v1 = (const float*)d_in[13];
        g2  = (const float*)d_in[14]; b2 = (const float*)d_in[15];
        m2  = (const float*)d_in[16]; v2 = (const float*)d_in[17];
        g3  = (const float*)d_in[18]; b3 = (const float*)d_in[19];
        m3  = (const float*)d_in[20]; v3 = (const float*)d_in[21];
    }
    float* out = (float*)d_out;

    uint32_t *xp, *h1, *h2, *h3, *h4, *h5, *wo1, *wq1, *wo2, *wq2, *wo3, *wq3;
    float *sc1, *bi1, *sc2, *bi2, *sc3, *bi3;
    cudaGetSymbolAddress((void**)&xp,  g_xp);
    cudaGetSymbolAddress((void**)&h1,  g_h1);
    cudaGetSymbolAddress((void**)&h2,  g_h2);
    cudaGetSymbolAddress((void**)&h3,  g_h3);
    cudaGetSymbolAddress((void**)&h4,  g_h4);
    cudaGetSymbolAddress((void**)&h5,  g_h5);
    cudaGetSymbolAddress((void**)&wo1, g_wo1);
    cudaGetSymbolAddress((void**)&wq1, g_w1);
    cudaGetSymbolAddress((void**)&wo2, g_wo2);
    cudaGetSymbolAddress((void**)&wq2, g_w2);
    cudaGetSymbolAddress((void**)&wo3, g_wo3);
    cudaGetSymbolAddress((void**)&wq3, g_w3);
    cudaGetSymbolAddress((void**)&sc1, g_sc1);
    cudaGetSymbolAddress((void**)&bi1, g_bi1);
    cudaGetSymbolAddress((void**)&sc2, g_sc2);
    cudaGetSymbolAddress((void**)&bi2, g_bi2);
    cudaGetSymbolAddress((void**)&sc3, g_sc3);
    cudaGetSymbolAddress((void**)&bi3, g_bi3);

    cudaFuncSetAttribute(mmaconv<9,0>, cudaFuncAttributeMaxDynamicSharedMemorySize, DSMEM);
    cudaFuncSetAttribute(mmaconv<1,1>, cudaFuncAttributeMaxDynamicSharedMemorySize, DSMEM);
    cudaFuncSetAttribute(mmaconv<9,1>, cudaFuncAttributeMaxDynamicSharedMemorySize, DSMEM);
    cudaFuncSetAttribute(mmaconv<1,2>, cudaFuncAttributeMaxDynamicSharedMemorySize, DSMEM);

    bnprep_kernel<<<1, 256>>>(g1, b1, m1, v1, sc1, bi1, 256);
    bnprep_kernel<<<1, 256>>>(g2, b2, m2, v2, sc2, bi2, 256);
    bnprep_kernel<<<4, 256>>>(g3, b3, m3, v3, sc3, bi3, 1024);

    { int n = BBN * 1024 * HWN;    xprep_kernel<<<(n + 255) / 256, 256>>>(x, xp, n); }
    { int n = 2048 * 1024 * 9;     wprep_kernel<<<(n + 255) / 256, 256>>>(ow1, wo1, 1024, 9, n); }
    { int n = 256 * 1024;          wprep_kernel<<<(n + 255) / 256, 256>>>(w1,  wq1, 1024, 1, n); }
    { int n = 512 * 256 * 9;       wprep_kernel<<<(n + 255) / 256, 256>>>(ow2, wo2, 256, 9, n); }
    { int n = 256 * 256 * 9;       wprep_kernel<<<(n + 255) / 256, 256>>>(w2,  wq2, 256, 9, n); }
    { int n = 512 * 256 * 9;       wprep_kernel<<<(n + 255) / 256, 256>>>(ow3, wo3, 256, 9, n); }
    { int n = 1024 * 256;          wprep_kernel<<<(n + 255) / 256, 256>>>(w3,  wq3, 256, 1, n); }

    const dim3 blk(256);
    mmaconv<9,0><<<dim3(128, 16), blk, DSMEM>>>(xp, wo1, ob1, nullptr, nullptr, h1, nullptr, 1024, 2048);
    mmaconv<1,1><<<dim3(128, 2),  blk, DSMEM>>>(h1, wq1, nullptr, sc1, bi1, h2, nullptr, 1024, 256);
    mmaconv<9,0><<<dim3(128, 4),  blk, DSMEM>>>(h2, wo2, ob2, nullptr, nullptr, h3, nullptr, 256, 512);
    mmaconv<9,1><<<dim3(128, 2),  blk, DSMEM>>>(h3, wq2, nullptr, sc2, bi2, h4, nullptr, 256, 256);
    mmaconv<9,0><<<dim3(128, 4),  blk, DSMEM>>>(h4, wo3, ob3, nullptr, nullptr, h5, nullptr, 256, 512);
    mmaconv<1,2><<<dim3(128, 8),  blk, DSMEM>>>(h5, wq3, nullptr, sc3, bi3, nullptr, out, 256, 1024);
}